// round 8
// baseline (speedup 1.0000x reference)
#include <cuda_runtime.h>
#include <cuda_fp16.h>
#include <cstdint>

// ---------------- problem constants ----------------
#define NWIN    4096
#define NTOK    49
#define HID     384
#define NHEAD   12
#define DHEAD   32
#define MTOT    (NWIN*NTOK)          // 200704
#define QSCALE  0.17677669529663687f // 32^-0.5

// ---------------- device scratch ----------------
__device__ float g_ao[(size_t)MTOT * HID];   // attention output [m][h*32+d]
__device__ float g_bias[NHEAD * NTOK * NTOK];

// ---------------- mma.sync m16n8k16 fp16 -> fp32 ----------------
__device__ __forceinline__ void mma_f16(float c[4], const uint32_t a[4], const uint32_t b[2]) {
    asm volatile(
        "mma.sync.aligned.m16n8k16.row.col.f32.f16.f16.f32 "
        "{%0,%1,%2,%3}, {%4,%5,%6,%7}, {%8,%9}, {%0,%1,%2,%3};\n"
        : "+f"(c[0]), "+f"(c[1]), "+f"(c[2]), "+f"(c[3])
        : "r"(a[0]), "r"(a[1]), "r"(a[2]), "r"(a[3]),
          "r"(b[0]), "r"(b[1]));
}

__device__ __forceinline__ uint32_t ld_h2(const __half* p) {
    return *reinterpret_cast<const uint32_t*>(p);
}

__device__ __forceinline__ void split_store(__half* hi, __half* lo, float a, float b) {
    __half2 h, l;
    h.x = __float2half_rn(a); l.x = __float2half_rn(a - __half2float(h.x));
    h.y = __float2half_rn(b); l.y = __float2half_rn(b - __half2float(h.y));
    *reinterpret_cast<__half2*>(hi) = h;
    *reinterpret_cast<__half2*>(lo) = l;
}

// ---------------- K0: dense relative position bias ----------------
__global__ void bias_kernel(const float* __restrict__ table, const int* __restrict__ ridx) {
    int e = blockIdx.x * 256 + threadIdx.x;
    if (e < NHEAD * NTOK * NTOK) {
        int h = e / (NTOK * NTOK);
        int r = e - h * (NTOK * NTOK);
        g_bias[e] = table[ridx[r] * NHEAD + h];
    }
}

// ================= fused QKV + attention kernel =================
// Block = one window (49 tokens). 256 threads (8 warps).
// A (x window) resident in smem as fp16 hi/lo, 64 rows padded, stride 392.
// Per head: GEMM C[64x96] (B streamed) -> scatter to Q/K/V smem -> scores ->
// softmax+bias -> PV -> g_ao.
struct FusedSmem {
    __half Ah[64 * 392];   // 50176 B
    __half Al[64 * 392];   // 50176 B
    __half Bh[96 * 40];    //  7680 B
    __half Bl[96 * 40];    //  7680 B
    union {
        struct { __half Qh[64 * 40], Ql[64 * 40], Kh[64 * 40], Kl[64 * 40]; } qk; // 20480 B
        struct { __half Ph[64 * 72], Pl[64 * 72]; } p;                             // 18432 B
    } u;                   // 20480 B
    __half Vth[32 * 72];   //  4608 B  (V transposed [d][token])
    __half Vtl[32 * 72];   //  4608 B
    float  sc[64 * 57];    // 14592 B  (raw scores)
};                          // total 160000 B

__global__ void __launch_bounds__(256) qkvattn_kernel(const float* __restrict__ x,
                                                      const float* __restrict__ qkv_w,
                                                      const float* __restrict__ qkv_b) {
    extern __shared__ char smem_raw[];
    FusedSmem& sm = *reinterpret_cast<FusedSmem*>(smem_raw);

    const int ww   = blockIdx.x;
    const int tid  = threadIdx.x;
    const int lane = tid & 31;
    const int wid  = tid >> 5;
    const int rr   = lane >> 2;
    const int qoff = (lane & 3) << 1;
    const int lr   = tid >> 3;          // 0..31
    const int lc   = (tid & 7) << 2;    // 0,4..28

    const int wm2 = wid & 1,  wn4 = wid >> 1;   // GEMM warp grid 2M x 4N (tile 32x24)
    const int wm4 = wid & 3,  wn2 = wid >> 2;   // attn warp grid 4M x 2N

    // ---- phase 0: zero A (pad rows must be 0), load + split x window ----
    {
        uint4* z = reinterpret_cast<uint4*>(sm.Ah);
        const int nz = (64 * 392 * 2 * 2) / 16;   // Ah+Al bytes / 16
        for (int i = tid; i < nz; i += 256) z[i] = make_uint4(0, 0, 0, 0);
    }
    __syncthreads();
    for (int e = tid; e < 49 * 96; e += 256) {
        int row = e / 96;
        int c4  = (e - row * 96) * 4;
        float4 v = *reinterpret_cast<const float4*>(x + ((size_t)ww * 49 + row) * 384 + c4);
        split_store(&sm.Ah[row * 392 + c4],     &sm.Al[row * 392 + c4],     v.x, v.y);
        split_store(&sm.Ah[row * 392 + c4 + 2], &sm.Al[row * 392 + c4 + 2], v.z, v.w);
    }
    // first __syncthreads inside the GEMM loop covers this

    for (int h = 0; h < NHEAD; h++) {
        // ================= GEMM: C[64x96] = A @ W_h^T =================
        float acc[2][3][4];
        #pragma unroll
        for (int a = 0; a < 2; a++)
            #pragma unroll
            for (int b = 0; b < 3; b++)
                #pragma unroll
                for (int c = 0; c < 4; c++) acc[a][b][c] = 0.f;

        const float* Bbase = qkv_w + (size_t)(h * 96 + lr) * 384 + lc;
        float4 rbv[3];
        #pragma unroll
        for (int p = 0; p < 3; p++)
            rbv[p] = *reinterpret_cast<const float4*>(Bbase + (size_t)p * 32 * 384);

        for (int k0 = 0; k0 < 384; k0 += 32) {
            __syncthreads();
            #pragma unroll
            for (int p = 0; p < 3; p++) {
                int row = lr + p * 32;
                split_store(&sm.Bh[row * 40 + lc],     &sm.Bl[row * 40 + lc],     rbv[p].x, rbv[p].y);
                split_store(&sm.Bh[row * 40 + lc + 2], &sm.Bl[row * 40 + lc + 2], rbv[p].z, rbv[p].w);
            }
            __syncthreads();
            if (k0 + 32 < 384) {
                #pragma unroll
                for (int p = 0; p < 3; p++)
                    rbv[p] = *reinterpret_cast<const float4*>(Bbase + (size_t)p * 32 * 384 + k0 + 32);
            }
            #pragma unroll
            for (int ks = 0; ks < 32; ks += 16) {
                const int cA = k0 + ks + qoff;   // A resident: global K col
                const int cB = ks + qoff;        // B tile: local col
                uint32_t ah[2][4], al[2][4];
                #pragma unroll
                for (int mt = 0; mt < 2; mt++) {
                    int rbr = wm2 * 32 + mt * 16 + rr;
                    ah[mt][0] = ld_h2(&sm.Ah[rbr * 392 + cA]);
                    ah[mt][1] = ld_h2(&sm.Ah[(rbr + 8) * 392 + cA]);
                    ah[mt][2] = ld_h2(&sm.Ah[rbr * 392 + cA + 8]);
                    ah[mt][3] = ld_h2(&sm.Ah[(rbr + 8) * 392 + cA + 8]);
                    al[mt][0] = ld_h2(&sm.Al[rbr * 392 + cA]);
                    al[mt][1] = ld_h2(&sm.Al[(rbr + 8) * 392 + cA]);
                    al[mt][2] = ld_h2(&sm.Al[rbr * 392 + cA + 8]);
                    al[mt][3] = ld_h2(&sm.Al[(rbr + 8) * 392 + cA + 8]);
                }
                #pragma unroll
                for (int nt = 0; nt < 3; nt++) {
                    int nb = wn4 * 24 + nt * 8 + rr;
                    uint32_t bh[2], bl[2];
                    bh[0] = ld_h2(&sm.Bh[nb * 40 + cB]);
                    bh[1] = ld_h2(&sm.Bh[nb * 40 + cB + 8]);
                    bl[0] = ld_h2(&sm.Bl[nb * 40 + cB]);
                    bl[1] = ld_h2(&sm.Bl[nb * 40 + cB + 8]);
                    #pragma unroll
                    for (int mt = 0; mt < 2; mt++) {
                        mma_f16(acc[mt][nt], ah[mt], bh);
                        mma_f16(acc[mt][nt], ah[mt], bl);
                        mma_f16(acc[mt][nt], al[mt], bh);
                    }
                }
            }
        }
        __syncthreads();

        // ====== scatter epilogue: frags + bias (+scale) -> Q/K/V split smem ======
        #pragma unroll
        for (int mt = 0; mt < 2; mt++)
            #pragma unroll
            for (int nt = 0; nt < 3; nt++) {
                const int r0 = wm2 * 32 + mt * 16 + rr;
                const int c0 = wn4 * 24 + nt * 8 + qoff;
                #pragma unroll
                for (int q = 0; q < 4; q++) {
                    int r   = r0 + ((q >> 1) << 3);
                    int col = c0 + (q & 1);
                    float val = acc[mt][nt][q] + qkv_b[h * 96 + col];
                    int dd = col / 3;
                    int sp = col - dd * 3;
                    if (sp == 0) val *= QSCALE;
                    __half hi = __float2half_rn(val);
                    __half lo = __float2half_rn(val - __half2float(hi));
                    if (sp == 0)      { sm.u.qk.Qh[r * 40 + dd] = hi; sm.u.qk.Ql[r * 40 + dd] = lo; }
                    else if (sp == 1) { sm.u.qk.Kh[r * 40 + dd] = hi; sm.u.qk.Kl[r * 40 + dd] = lo; }
                    else              { sm.Vth[dd * 72 + r]     = hi; sm.Vtl[dd * 72 + r]     = lo; }
                }
            }
        __syncthreads();

        // ====== scores: S[64x56] = Q @ K^T  (warps 4M x 2N) ======
        {
            float sa[4][4];
            #pragma unroll
            for (int nt = 0; nt < 4; nt++)
                #pragma unroll
                for (int c = 0; c < 4; c++) sa[nt][c] = 0.f;
            const int nNT = (wn2 == 0) ? 4 : 3;

            #pragma unroll
            for (int kt = 0; kt < 32; kt += 16) {
                const int cc = kt + qoff;
                const int rbr = wm4 * 16 + rr;
                uint32_t ah[4], al[4];
                ah[0] = ld_h2(&sm.u.qk.Qh[rbr * 40 + cc]);
                ah[1] = ld_h2(&sm.u.qk.Qh[(rbr + 8) * 40 + cc]);
                ah[2] = ld_h2(&sm.u.qk.Qh[rbr * 40 + cc + 8]);
                ah[3] = ld_h2(&sm.u.qk.Qh[(rbr + 8) * 40 + cc + 8]);
                al[0] = ld_h2(&sm.u.qk.Ql[rbr * 40 + cc]);
                al[1] = ld_h2(&sm.u.qk.Ql[(rbr + 8) * 40 + cc]);
                al[2] = ld_h2(&sm.u.qk.Ql[rbr * 40 + cc + 8]);
                al[3] = ld_h2(&sm.u.qk.Ql[(rbr + 8) * 40 + cc + 8]);
                #pragma unroll
                for (int nt = 0; nt < 4; nt++) {
                    if (nt < nNT) {
                        const int nb = wn2 * 32 + nt * 8 + rr;
                        uint32_t bh[2], bl[2];
                        bh[0] = ld_h2(&sm.u.qk.Kh[nb * 40 + cc]);
                        bh[1] = ld_h2(&sm.u.qk.Kh[nb * 40 + cc + 8]);
                        bl[0] = ld_h2(&sm.u.qk.Kl[nb * 40 + cc]);
                        bl[1] = ld_h2(&sm.u.qk.Kl[nb * 40 + cc + 8]);
                        mma_f16(sa[nt], ah, bh);
                        mma_f16(sa[nt], ah, bl);
                        mma_f16(sa[nt], al, bh);
                    }
                }
            }
            const int r0 = wm4 * 16 + rr;
            #pragma unroll
            for (int nt = 0; nt < 4; nt++) {
                if (nt < nNT) {
                    const int c = wn2 * 32 + nt * 8 + qoff;
                    sm.sc[r0 * 57 + c]           = sa[nt][0];
                    sm.sc[r0 * 57 + c + 1]       = sa[nt][1];
                    sm.sc[(r0 + 8) * 57 + c]     = sa[nt][2];
                    sm.sc[(r0 + 8) * 57 + c + 1] = sa[nt][3];
                }
            }
        }
        __syncthreads();

        // ====== softmax (+bias) rows -> P split fp16 (over qk union) ======
        {
            const float* bias = &g_bias[h * (NTOK * NTOK)];
            for (int i = wid; i < NTOK; i += 8) {
                const int j2 = 32 + lane;
                const bool v2 = (j2 < NTOK);
                float s0 = sm.sc[i * 57 + lane] + bias[i * 49 + lane];
                float s1 = v2 ? (sm.sc[i * 57 + j2] + bias[i * 49 + j2]) : -3.0e38f;
                float mx = fmaxf(s0, s1);
                #pragma unroll
                for (int o = 16; o; o >>= 1) mx = fmaxf(mx, __shfl_xor_sync(0xffffffffu, mx, o));
                float p0 = expf(s0 - mx);
                float p1 = v2 ? expf(s1 - mx) : 0.f;
                float sum = p0 + p1;
                #pragma unroll
                for (int o = 16; o; o >>= 1) sum += __shfl_xor_sync(0xffffffffu, sum, o);
                float inv = 1.f / sum;
                p0 *= inv;
                p1 = v2 ? p1 * inv : 0.f;
                __half hi0 = __float2half_rn(p0);
                __half lo0 = __float2half_rn(p0 - __half2float(hi0));
                sm.u.p.Ph[i * 72 + lane] = hi0;
                sm.u.p.Pl[i * 72 + lane] = lo0;
                __half hi1 = __float2half_rn(p1);
                __half lo1 = __float2half_rn(p1 - __half2float(hi1));
                sm.u.p.Ph[i * 72 + j2] = hi1;
                sm.u.p.Pl[i * 72 + j2] = lo1;
            }
        }
        __syncthreads();

        // ====== PV: O[64x32] = P[64x64] @ V  (warps 4M x 2N, nt=2) ======
        {
            float pa[2][4];
            #pragma unroll
            for (int nt = 0; nt < 2; nt++)
                #pragma unroll
                for (int c = 0; c < 4; c++) pa[nt][c] = 0.f;

            #pragma unroll
            for (int kt = 0; kt < 64; kt += 16) {
                const int cc = kt + qoff;
                const int rbr = wm4 * 16 + rr;
                uint32_t ah[4], al[4];
                ah[0] = ld_h2(&sm.u.p.Ph[rbr * 72 + cc]);
                ah[1] = ld_h2(&sm.u.p.Ph[(rbr + 8) * 72 + cc]);
                ah[2] = ld_h2(&sm.u.p.Ph[rbr * 72 + cc + 8]);
                ah[3] = ld_h2(&sm.u.p.Ph[(rbr + 8) * 72 + cc + 8]);
                al[0] = ld_h2(&sm.u.p.Pl[rbr * 72 + cc]);
                al[1] = ld_h2(&sm.u.p.Pl[(rbr + 8) * 72 + cc]);
                al[2] = ld_h2(&sm.u.p.Pl[rbr * 72 + cc + 8]);
                al[3] = ld_h2(&sm.u.p.Pl[(rbr + 8) * 72 + cc + 8]);
                #pragma unroll
                for (int nt = 0; nt < 2; nt++) {
                    const int nb = wn2 * 16 + nt * 8 + rr;
                    uint32_t bh[2], bl[2];
                    bh[0] = ld_h2(&sm.Vth[nb * 72 + cc]);
                    bh[1] = ld_h2(&sm.Vth[nb * 72 + cc + 8]);
                    bl[0] = ld_h2(&sm.Vtl[nb * 72 + cc]);
                    bl[1] = ld_h2(&sm.Vtl[nb * 72 + cc + 8]);
                    mma_f16(pa[nt], ah, bh);
                    mma_f16(pa[nt], ah, bl);
                    mma_f16(pa[nt], al, bh);
                }
            }
            const int r0 = wm4 * 16 + rr;
            #pragma unroll
            for (int nt = 0; nt < 2; nt++) {
                const int d = wn2 * 16 + nt * 8 + qoff;
                if (r0 < NTOK) {
                    float2 v = make_float2(pa[nt][0], pa[nt][1]);
                    *reinterpret_cast<float2*>(&g_ao[((size_t)ww * NTOK + r0) * HID + h * DHEAD + d]) = v;
                }
                if (r0 + 8 < NTOK) {
                    float2 v = make_float2(pa[nt][2], pa[nt][3]);
                    *reinterpret_cast<float2*>(&g_ao[((size_t)ww * NTOK + r0 + 8) * HID + h * DHEAD + d]) = v;
                }
            }
        }
        // next head's GEMM begins with __syncthreads()
    }
}

// ================= K3: output projection (unchanged) =================
struct SmemGemm {
    __half Ah[128 * 40];
    __half Al[128 * 40];
    __half Bh[96 * 40];
    __half Bl[96 * 40];
};
union SmemU {
    SmemGemm g;
    float    c[128 * 96];
};

__device__ __forceinline__ void run_gemm(const float* __restrict__ A,
                                         const float* __restrict__ B,
                                         int m0, int n0,
                                         SmemGemm* sm, float acc[2][6][4]) {
    const int tid  = threadIdx.x;
    const int lane = tid & 31;
    const int wid  = tid >> 5;
    const int wm   = wid & 3;
    const int wn   = wid >> 2;
    const int lr   = tid >> 3;
    const int lc   = (tid & 7) << 2;

    const float* Abase = A + (size_t)(m0 + lr) * 384 + lc;
    const float* Bbase = B + (size_t)(n0 + lr) * 384 + lc;

    float4 ra[4], rb[3];
    #pragma unroll
    for (int p = 0; p < 4; p++)
        ra[p] = *reinterpret_cast<const float4*>(Abase + (size_t)p * 32 * 384);
    #pragma unroll
    for (int p = 0; p < 3; p++)
        rb[p] = *reinterpret_cast<const float4*>(Bbase + (size_t)p * 32 * 384);

    for (int k0 = 0; k0 < 384; k0 += 32) {
        __syncthreads();
        #pragma unroll
        for (int p = 0; p < 4; p++) {
            int row = lr + p * 32;
            split_store(&sm->Ah[row * 40 + lc],     &sm->Al[row * 40 + lc],     ra[p].x, ra[p].y);
            split_store(&sm->Ah[row * 40 + lc + 2], &sm->Al[row * 40 + lc + 2], ra[p].z, ra[p].w);
        }
        #pragma unroll
        for (int p = 0; p < 3; p++) {
            int row = lr + p * 32;
            split_store(&sm->Bh[row * 40 + lc],     &sm->Bl[row * 40 + lc],     rb[p].x, rb[p].y);
            split_store(&sm->Bh[row * 40 + lc + 2], &sm->Bl[row * 40 + lc + 2], rb[p].z, rb[p].w);
        }
        __syncthreads();

        if (k0 + 32 < 384) {
            #pragma unroll
            for (int p = 0; p < 4; p++)
                ra[p] = *reinterpret_cast<const float4*>(Abase + (size_t)p * 32 * 384 + k0 + 32);
            #pragma unroll
            for (int p = 0; p < 3; p++)
                rb[p] = *reinterpret_cast<const float4*>(Bbase + (size_t)p * 32 * 384 + k0 + 32);
        }

        #pragma unroll
        for (int ks = 0; ks < 32; ks += 16) {
            uint32_t ah[2][4], al[2][4], bh[6][2], bl[6][2];
            const int rr = lane >> 2;
            const int cc = ks + ((lane & 3) << 1);
            #pragma unroll
            for (int mt = 0; mt < 2; mt++) {
                int rb2 = wm * 32 + mt * 16 + rr;
                ah[mt][0] = ld_h2(&sm->Ah[rb2 * 40 + cc]);
                ah[mt][1] = ld_h2(&sm->Ah[(rb2 + 8) * 40 + cc]);
                ah[mt][2] = ld_h2(&sm->Ah[rb2 * 40 + cc + 8]);
                ah[mt][3] = ld_h2(&sm->Ah[(rb2 + 8) * 40 + cc + 8]);
                al[mt][0] = ld_h2(&sm->Al[rb2 * 40 + cc]);
                al[mt][1] = ld_h2(&sm->Al[(rb2 + 8) * 40 + cc]);
                al[mt][2] = ld_h2(&sm->Al[rb2 * 40 + cc + 8]);
                al[mt][3] = ld_h2(&sm->Al[(rb2 + 8) * 40 + cc + 8]);
            }
            #pragma unroll
            for (int nt = 0; nt < 6; nt++) {
                int nb = wn * 48 + nt * 8 + rr;
                bh[nt][0] = ld_h2(&sm->Bh[nb * 40 + cc]);
                bh[nt][1] = ld_h2(&sm->Bh[nb * 40 + cc + 8]);
                bl[nt][0] = ld_h2(&sm->Bl[nb * 40 + cc]);
                bl[nt][1] = ld_h2(&sm->Bl[nb * 40 + cc + 8]);
            }
            #pragma unroll
            for (int mt = 0; mt < 2; mt++)
                #pragma unroll
                for (int nt = 0; nt < 6; nt++) {
                    mma_f16(acc[mt][nt], ah[mt], bh[nt]);
                    mma_f16(acc[mt][nt], ah[mt], bl[nt]);
                    mma_f16(acc[mt][nt], al[mt], bh[nt]);
                }
        }
    }
}

__global__ void __launch_bounds__(256) fc_kernel(const float* __restrict__ fc_w,
                                                 const float* __restrict__ fc_b,
                                                 float* __restrict__ out) {
    __shared__ SmemU sm;
    float acc[2][6][4];
    #pragma unroll
    for (int a = 0; a < 2; a++)
        #pragma unroll
        for (int b = 0; b < 6; b++)
            #pragma unroll
            for (int c = 0; c < 4; c++) acc[a][b][c] = 0.f;

    const int n0 = blockIdx.x * 96;
    const int m0 = blockIdx.y * 128;
    run_gemm(g_ao, fc_w, m0, n0, &sm.g, acc);

    const int lane = threadIdx.x & 31, wid = threadIdx.x >> 5;
    const int wm = wid & 3, wn = wid >> 2;
    const int rr = lane >> 2, c2 = (lane & 3) << 1;
    #pragma unroll
    for (int mt = 0; mt < 2; mt++)
        #pragma unroll
        for (int nt = 0; nt < 6; nt++) {
            int row = m0 + wm * 32 + mt * 16 + rr;
            int col = n0 + wn * 48 + nt * 8 + c2;
            float b0 = fc_b[col], b1 = fc_b[col + 1];
            float2 v0 = make_float2(acc[mt][nt][0] + b0, acc[mt][nt][1] + b1);
            float2 v1 = make_float2(acc[mt][nt][2] + b0, acc[mt][nt][3] + b1);
            *reinterpret_cast<float2*>(&out[(size_t)row * 384 + col])       = v0;
            *reinterpret_cast<float2*>(&out[(size_t)(row + 8) * 384 + col]) = v1;
        }
}

// ---------------- launch ----------------
extern "C" void kernel_launch(void* const* d_in, const int* in_sizes, int n_in,
                              void* d_out, int out_size) {
    const float* x    = (const float*)d_in[0];
    const float* tbl  = (const float*)d_in[1];
    const float* qw   = (const float*)d_in[2];
    const float* qb   = (const float*)d_in[3];
    const float* fw   = (const float*)d_in[4];
    const float* fb   = (const float*)d_in[5];
    const int*   ridx = (const int*)d_in[6];
    float* out = (float*)d_out;

    cudaFuncSetAttribute(qkvattn_kernel,
                         cudaFuncAttributeMaxDynamicSharedMemorySize,
                         (int)sizeof(FusedSmem));

    bias_kernel<<<(NHEAD * NTOK * NTOK + 255) / 256, 256>>>(tbl, ridx);
    qkvattn_kernel<<<NWIN, 256, sizeof(FusedSmem)>>>(x, qw, qb);
    fc_kernel<<<dim3(HID / 96, MTOT / 128), 256>>>(fw, fb, out);
}

// round 9
// speedup vs baseline: 2.5011x; 2.5011x over previous
#include <cuda_runtime.h>
#include <cuda_fp16.h>
#include <cstdint>

// ---------------- problem constants ----------------
#define NWIN    4096
#define NTOK    49
#define HID     384
#define NHEAD   12
#define DHEAD   32
#define MTOT    (NWIN*NTOK)          // 200704
#define QSCALE  0.17677669529663687f // 32^-0.5

// ---------------- device scratch ----------------
__device__ float g_q[(size_t)MTOT * HID];    // [win][head][tok][d]
__device__ float g_k[(size_t)MTOT * HID];
__device__ float g_v[(size_t)MTOT * HID];
__device__ float g_ao[(size_t)MTOT * HID];   // attention output [m][h*32+d]
__device__ float g_bias[NHEAD * NTOK * NTOK];

// ---------------- shared memory layout for GEMM kernels ----------------
struct SmemGemm {
    __half Ah[128 * 40];
    __half Al[128 * 40];
    __half Bh[96 * 40];
    __half Bl[96 * 40];
};
union SmemU {
    SmemGemm g;
    float    c[128 * 96];
};

// ---------------- mma.sync m16n8k16 fp16 -> fp32 ----------------
__device__ __forceinline__ void mma_f16(float c[4], const uint32_t a[4], const uint32_t b[2]) {
    asm volatile(
        "mma.sync.aligned.m16n8k16.row.col.f32.f16.f16.f32 "
        "{%0,%1,%2,%3}, {%4,%5,%6,%7}, {%8,%9}, {%0,%1,%2,%3};\n"
        : "+f"(c[0]), "+f"(c[1]), "+f"(c[2]), "+f"(c[3])
        : "r"(a[0]), "r"(a[1]), "r"(a[2]), "r"(a[3]),
          "r"(b[0]), "r"(b[1]));
}

__device__ __forceinline__ uint32_t ld_h2(const __half* p) {
    return *reinterpret_cast<const uint32_t*>(p);
}

__device__ __forceinline__ void split_store(__half* hi, __half* lo, float a, float b) {
    __half2 h, l;
    h.x = __float2half_rn(a); l.x = __float2half_rn(a - __half2float(h.x));
    h.y = __float2half_rn(b); l.y = __float2half_rn(b - __half2float(h.y));
    *reinterpret_cast<__half2*>(hi) = h;
    *reinterpret_cast<__half2*>(lo) = l;
}

__device__ __forceinline__ void cp16(uint32_t smem_addr, const void* gptr) {
    asm volatile("cp.async.cg.shared.global [%0], [%1], 16;\n"
                 :: "r"(smem_addr), "l"(gptr));
}

// ---------------- shared GEMM mainloop (K1/K3): C[128x96] = A * B^T ----------------
__device__ __forceinline__ void run_gemm(const float* __restrict__ A,
                                         const float* __restrict__ B,
                                         int m0, int n0,
                                         SmemGemm* sm, float acc[2][6][4]) {
    const int tid  = threadIdx.x;
    const int lane = tid & 31;
    const int wid  = tid >> 5;
    const int wm   = wid & 3;
    const int wn   = wid >> 2;
    const int lr   = tid >> 3;
    const int lc   = (tid & 7) << 2;

    const float* Abase = A + (size_t)(m0 + lr) * 384 + lc;
    const float* Bbase = B + (size_t)(n0 + lr) * 384 + lc;

    float4 ra[4], rb[3];
    #pragma unroll
    for (int p = 0; p < 4; p++)
        ra[p] = *reinterpret_cast<const float4*>(Abase + (size_t)p * 32 * 384);
    #pragma unroll
    for (int p = 0; p < 3; p++)
        rb[p] = *reinterpret_cast<const float4*>(Bbase + (size_t)p * 32 * 384);

    for (int k0 = 0; k0 < 384; k0 += 32) {
        __syncthreads();
        #pragma unroll
        for (int p = 0; p < 4; p++) {
            int row = lr + p * 32;
            split_store(&sm->Ah[row * 40 + lc],     &sm->Al[row * 40 + lc],     ra[p].x, ra[p].y);
            split_store(&sm->Ah[row * 40 + lc + 2], &sm->Al[row * 40 + lc + 2], ra[p].z, ra[p].w);
        }
        #pragma unroll
        for (int p = 0; p < 3; p++) {
            int row = lr + p * 32;
            split_store(&sm->Bh[row * 40 + lc],     &sm->Bl[row * 40 + lc],     rb[p].x, rb[p].y);
            split_store(&sm->Bh[row * 40 + lc + 2], &sm->Bl[row * 40 + lc + 2], rb[p].z, rb[p].w);
        }
        __syncthreads();

        if (k0 + 32 < 384) {
            #pragma unroll
            for (int p = 0; p < 4; p++)
                ra[p] = *reinterpret_cast<const float4*>(Abase + (size_t)p * 32 * 384 + k0 + 32);
            #pragma unroll
            for (int p = 0; p < 3; p++)
                rb[p] = *reinterpret_cast<const float4*>(Bbase + (size_t)p * 32 * 384 + k0 + 32);
        }

        #pragma unroll
        for (int ks = 0; ks < 32; ks += 16) {
            uint32_t ah[2][4], al[2][4], bh[6][2], bl[6][2];
            const int rr = lane >> 2;
            const int cc = ks + ((lane & 3) << 1);
            #pragma unroll
            for (int mt = 0; mt < 2; mt++) {
                int rb2 = wm * 32 + mt * 16 + rr;
                ah[mt][0] = ld_h2(&sm->Ah[rb2 * 40 + cc]);
                ah[mt][1] = ld_h2(&sm->Ah[(rb2 + 8) * 40 + cc]);
                ah[mt][2] = ld_h2(&sm->Ah[rb2 * 40 + cc + 8]);
                ah[mt][3] = ld_h2(&sm->Ah[(rb2 + 8) * 40 + cc + 8]);
                al[mt][0] = ld_h2(&sm->Al[rb2 * 40 + cc]);
                al[mt][1] = ld_h2(&sm->Al[(rb2 + 8) * 40 + cc]);
                al[mt][2] = ld_h2(&sm->Al[rb2 * 40 + cc + 8]);
                al[mt][3] = ld_h2(&sm->Al[(rb2 + 8) * 40 + cc + 8]);
            }
            #pragma unroll
            for (int nt = 0; nt < 6; nt++) {
                int nb = wn * 48 + nt * 8 + rr;
                bh[nt][0] = ld_h2(&sm->Bh[nb * 40 + cc]);
                bh[nt][1] = ld_h2(&sm->Bh[nb * 40 + cc + 8]);
                bl[nt][0] = ld_h2(&sm->Bl[nb * 40 + cc]);
                bl[nt][1] = ld_h2(&sm->Bl[nb * 40 + cc + 8]);
            }
            #pragma unroll
            for (int mt = 0; mt < 2; mt++)
                #pragma unroll
                for (int nt = 0; nt < 6; nt++) {
                    mma_f16(acc[mt][nt], ah[mt], bh[nt]);
                    mma_f16(acc[mt][nt], ah[mt], bl[nt]);
                    mma_f16(acc[mt][nt], al[mt], bh[nt]);
                }
        }
    }
}

// ---------------- K0: dense relative position bias ----------------
__global__ void bias_kernel(const float* __restrict__ table, const int* __restrict__ ridx) {
    int e = blockIdx.x * 256 + threadIdx.x;
    if (e < NHEAD * NTOK * NTOK) {
        int h = e / (NTOK * NTOK);
        int r = e - h * (NTOK * NTOK);
        g_bias[e] = table[ridx[r] * NHEAD + h];
    }
}

// ---------------- K1: QKV projection + scatter ----------------
__global__ void __launch_bounds__(256) qkv_kernel(const float* __restrict__ x,
                                                  const float* __restrict__ qkv_w,
                                                  const float* __restrict__ qkv_b) {
    __shared__ SmemU sm;
    float acc[2][6][4];
    #pragma unroll
    for (int a = 0; a < 2; a++)
        #pragma unroll
        for (int b = 0; b < 6; b++)
            #pragma unroll
            for (int c = 0; c < 4; c++) acc[a][b][c] = 0.f;

    const int n0 = blockIdx.x * 96;
    const int m0 = blockIdx.y * 128;
    run_gemm(x, qkv_w, m0, n0, &sm.g, acc);
    __syncthreads();

    const int lane = threadIdx.x & 31, wid = threadIdx.x >> 5;
    const int wm = wid & 3, wn = wid >> 2;
    const int rr = lane >> 2, c2 = (lane & 3) << 1;
    #pragma unroll
    for (int mt = 0; mt < 2; mt++)
        #pragma unroll
        for (int nt = 0; nt < 6; nt++) {
            int row = wm * 32 + mt * 16 + rr;
            int col = wn * 48 + nt * 8 + c2;
            sm.c[row * 96 + col]           = acc[mt][nt][0];
            sm.c[row * 96 + col + 1]       = acc[mt][nt][1];
            sm.c[(row + 8) * 96 + col]     = acc[mt][nt][2];
            sm.c[(row + 8) * 96 + col + 1] = acc[mt][nt][3];
        }
    __syncthreads();

    const int h = blockIdx.x;
    for (int e = threadIdx.x; e < 128 * 96; e += 256) {
        int dd  = e & 31;
        int t2  = e >> 5;
        int s   = t2 % 3;
        int row = t2 / 3;
        int col = dd * 3 + s;
        float val = sm.c[row * 96 + col] + qkv_b[n0 + col];
        int m = m0 + row;
        int ww = m / 49;
        int t  = m - ww * 49;
        size_t o = ((size_t)(ww * NHEAD + h) * NTOK + t) * DHEAD + dd;
        if (s == 0)      __stcs(&g_q[o], val * QSCALE);
        else if (s == 1) __stcs(&g_k[o], val);
        else             __stcs(&g_v[o], val);
    }
}

// ---------------- K2: per-(window,head) attention via fp16-split MMA ----------------
// cp.async staged loads: q,k staged into sc region; v staged into Kh/Kl region.
struct AttnSmem {
    union {
        struct {
            __half Qh[64 * 40];   //     0 ..  5120
            __half Ql[64 * 40];   //  5120 .. 10240
            __half Kh[64 * 40];   // 10240 .. 15360
            __half Kl[64 * 40];   // 15360 .. 20480
        } qk;
        struct {
            __half Ph[64 * 72];
            __half Pl[64 * 72];
        } p;
    } u;                   // 20480 B
    __half Vth[32 * 72];   // 20480 .. 25088  (V transposed [d][token], hi)
    __half Vtl[32 * 72];   // 25088 .. 29696  (lo)
    float  sc[64 * 57];    // 29696 .. 44288  (staging q/k, then raw scores)
};

__global__ void __launch_bounds__(128) attn_kernel() {
    const int bid = blockIdx.x;        // ww*NHEAD + h
    const int h   = bid % NHEAD;
    const int ww  = bid / NHEAD;

    __shared__ AttnSmem s;

    const int tid = threadIdx.x, lane = tid & 31, wm = tid >> 5;
    const int rr  = lane >> 2;
    const int qoff = (lane & 3) << 1;
    const size_t base = (size_t)bid * (NTOK * DHEAD);

    // staging addresses (shared-space u32)
    const uint32_t stage_q = (uint32_t)__cvta_generic_to_shared(s.sc);                 // 6272 B
    const uint32_t stage_k = stage_q + 6272;                                           // 6272 B
    const uint32_t stage_v = (uint32_t)__cvta_generic_to_shared(s.u.qk.Kh);            // 6272 B

    // issue async copies of q/k/v (392 x 16B each), then zero Vth/Vtl pads
    {
        const char* gq = (const char*)(g_q + base);
        const char* gk = (const char*)(g_k + base);
        const char* gv = (const char*)(g_v + base);
        for (int e = tid; e < 392; e += 128) {
            cp16(stage_q + e * 16, gq + e * 16);
            cp16(stage_k + e * 16, gk + e * 16);
            cp16(stage_v + e * 16, gv + e * 16);
        }
        asm volatile("cp.async.commit_group;\n");
        // zero Vt (incl. pad token-cols 49..63): 9216 B, disjoint from staging
        uint4* z = reinterpret_cast<uint4*>(s.Vth);
        for (int i = tid; i < 9216 / 16; i += 128) z[i] = make_uint4(0, 0, 0, 0);
        asm volatile("cp.async.wait_group 0;\n" ::: "memory");
    }
    __syncthreads();

    // phase 1: convert V (from staging in Kh/Kl region) -> Vth/Vtl
    {
        const float* sv = (const float*)s.u.qk.Kh;
        for (int e = tid; e < 392; e += 128) {
            int j = e >> 3;               // token 0..48
            int c = (e & 7) << 2;         // d 0,4..28
            float4 v4 = *reinterpret_cast<const float4*>(sv + e * 4);
            const float* vv = &v4.x;
            #pragma unroll
            for (int l = 0; l < 4; l++) {
                float val = vv[l];
                __half hi = __float2half_rn(val);
                __half lo = __float2half_rn(val - __half2float(hi));
                s.Vth[(c + l) * 72 + j] = hi;
                s.Vtl[(c + l) * 72 + j] = lo;
            }
        }
    }
    __syncthreads();

    // phase 2: convert Q and K (sources in sc staging, targets in u.qk)
    {
        const float* sq = (const float*)s.sc;
        const float* sk = sq + 1568;
        for (int e = tid; e < 392; e += 128) {
            int j = e >> 3;
            int c = (e & 7) << 2;
            float4 q4 = *reinterpret_cast<const float4*>(sq + e * 4);
            float4 k4 = *reinterpret_cast<const float4*>(sk + e * 4);
            split_store(&s.u.qk.Qh[j * 40 + c],     &s.u.qk.Ql[j * 40 + c],     q4.x, q4.y);
            split_store(&s.u.qk.Qh[j * 40 + c + 2], &s.u.qk.Ql[j * 40 + c + 2], q4.z, q4.w);
            split_store(&s.u.qk.Kh[j * 40 + c],     &s.u.qk.Kl[j * 40 + c],     k4.x, k4.y);
            split_store(&s.u.qk.Kh[j * 40 + c + 2], &s.u.qk.Kl[j * 40 + c + 2], k4.z, k4.w);
        }
    }
    __syncthreads();

    // ---- scores: S[64x56] = Q @ K^T (warp wm owns rows wm*16..+15) ----
    // Q/K pad rows (49..63) hold stale-but-row/col-local data; outputs for
    // those rows/cols are never read by softmax.
    {
        float acc[7][4];
        #pragma unroll
        for (int nt = 0; nt < 7; nt++)
            #pragma unroll
            for (int c = 0; c < 4; c++) acc[nt][c] = 0.f;

        #pragma unroll
        for (int kt = 0; kt < 32; kt += 16) {
            uint32_t ah[4], al[4];
            const int rb = wm * 16 + rr;
            const int cc = kt + qoff;
            ah[0] = ld_h2(&s.u.qk.Qh[rb * 40 + cc]);
            ah[1] = ld_h2(&s.u.qk.Qh[(rb + 8) * 40 + cc]);
            ah[2] = ld_h2(&s.u.qk.Qh[rb * 40 + cc + 8]);
            ah[3] = ld_h2(&s.u.qk.Qh[(rb + 8) * 40 + cc + 8]);
            al[0] = ld_h2(&s.u.qk.Ql[rb * 40 + cc]);
            al[1] = ld_h2(&s.u.qk.Ql[(rb + 8) * 40 + cc]);
            al[2] = ld_h2(&s.u.qk.Ql[rb * 40 + cc + 8]);
            al[3] = ld_h2(&s.u.qk.Ql[(rb + 8) * 40 + cc + 8]);
            #pragma unroll
            for (int nt = 0; nt < 7; nt++) {
                const int nb = nt * 8 + rr;
                uint32_t bh[2], bl[2];
                bh[0] = ld_h2(&s.u.qk.Kh[nb * 40 + cc]);
                bh[1] = ld_h2(&s.u.qk.Kh[nb * 40 + cc + 8]);
                bl[0] = ld_h2(&s.u.qk.Kl[nb * 40 + cc]);
                bl[1] = ld_h2(&s.u.qk.Kl[nb * 40 + cc + 8]);
                mma_f16(acc[nt], ah, bh);
                mma_f16(acc[nt], ah, bl);
                mma_f16(acc[nt], al, bh);
            }
        }
        __syncthreads();   // staging in sc fully consumed before overwriting with scores
        const int r0 = wm * 16 + rr;
        #pragma unroll
        for (int nt = 0; nt < 7; nt++) {
            const int c = nt * 8 + qoff;
            s.sc[r0 * 57 + c]           = acc[nt][0];
            s.sc[r0 * 57 + c + 1]       = acc[nt][1];
            s.sc[(r0 + 8) * 57 + c]     = acc[nt][2];
            s.sc[(r0 + 8) * 57 + c + 1] = acc[nt][3];
        }
    }
    __syncthreads();

    // ---- softmax (+bias) rows, write P split fp16 into union (Q/K dead) ----
    const float* bias = &g_bias[h * (NTOK * NTOK)];
    for (int i = wm; i < NTOK; i += 4) {
        const int j2 = 32 + lane;
        const bool v2 = (j2 < NTOK);
        float s0 = s.sc[i * 57 + lane] + bias[i * 49 + lane];
        float s1 = v2 ? (s.sc[i * 57 + j2] + bias[i * 49 + j2]) : -3.0e38f;
        float mx = fmaxf(s0, s1);
        #pragma unroll
        for (int o = 16; o; o >>= 1) mx = fmaxf(mx, __shfl_xor_sync(0xffffffffu, mx, o));
        float p0 = expf(s0 - mx);
        float p1 = v2 ? expf(s1 - mx) : 0.f;
        float sum = p0 + p1;
        #pragma unroll
        for (int o = 16; o; o >>= 1) sum += __shfl_xor_sync(0xffffffffu, sum, o);
        float inv = 1.f / sum;
        p0 *= inv;
        p1 = v2 ? p1 * inv : 0.f;
        {
            __half hi = __float2half_rn(p0);
            __half lo = __float2half_rn(p0 - __half2float(hi));
            s.u.p.Ph[i * 72 + lane] = hi;
            s.u.p.Pl[i * 72 + lane] = lo;
            __half hi1 = __float2half_rn(p1);
            __half lo1 = __float2half_rn(p1 - __half2float(hi1));
            s.u.p.Ph[i * 72 + j2] = hi1;
            s.u.p.Pl[i * 72 + j2] = lo1;
        }
    }
    __syncthreads();

    // ---- PV: O[64x32] = P[64x64] @ V  (Vt is col-major B) ----
    {
        float acc[4][4];
        #pragma unroll
        for (int nt = 0; nt < 4; nt++)
            #pragma unroll
            for (int c = 0; c < 4; c++) acc[nt][c] = 0.f;

        #pragma unroll
        for (int kt = 0; kt < 64; kt += 16) {
            uint32_t ah[4], al[4];
            const int rb = wm * 16 + rr;
            const int cc = kt + qoff;
            ah[0] = ld_h2(&s.u.p.Ph[rb * 72 + cc]);
            ah[1] = ld_h2(&s.u.p.Ph[(rb + 8) * 72 + cc]);
            ah[2] = ld_h2(&s.u.p.Ph[rb * 72 + cc + 8]);
            ah[3] = ld_h2(&s.u.p.Ph[(rb + 8) * 72 + cc + 8]);
            al[0] = ld_h2(&s.u.p.Pl[rb * 72 + cc]);
            al[1] = ld_h2(&s.u.p.Pl[(rb + 8) * 72 + cc]);
            al[2] = ld_h2(&s.u.p.Pl[rb * 72 + cc + 8]);
            al[3] = ld_h2(&s.u.p.Pl[(rb + 8) * 72 + cc + 8]);
            #pragma unroll
            for (int nt = 0; nt < 4; nt++) {
                const int nb = nt * 8 + rr;
                uint32_t bh[2], bl[2];
                bh[0] = ld_h2(&s.Vth[nb * 72 + cc]);
                bh[1] = ld_h2(&s.Vth[nb * 72 + cc + 8]);
                bl[0] = ld_h2(&s.Vtl[nb * 72 + cc]);
                bl[1] = ld_h2(&s.Vtl[nb * 72 + cc + 8]);
                mma_f16(acc[nt], ah, bh);
                mma_f16(acc[nt], ah, bl);
                mma_f16(acc[nt], al, bh);
            }
        }
        const int r0 = wm * 16 + rr;
        #pragma unroll
        for (int nt = 0; nt < 4; nt++) {
            const int d = nt * 8 + qoff;
            if (r0 < NTOK) {
                float2 v = make_float2(acc[nt][0], acc[nt][1]);
                *reinterpret_cast<float2*>(&g_ao[((size_t)ww * NTOK + r0) * HID + h * DHEAD + d]) = v;
            }
            if (r0 + 8 < NTOK) {
                float2 v = make_float2(acc[nt][2], acc[nt][3]);
                *reinterpret_cast<float2*>(&g_ao[((size_t)ww * NTOK + r0 + 8) * HID + h * DHEAD + d]) = v;
            }
        }
    }
}

// ---------------- K3: output projection ----------------
__global__ void __launch_bounds__(256) fc_kernel(const float* __restrict__ fc_w,
                                                 const float* __restrict__ fc_b,
                                                 float* __restrict__ out) {
    __shared__ SmemU sm;
    float acc[2][6][4];
    #pragma unroll
    for (int a = 0; a < 2; a++)
        #pragma unroll
        for (int b = 0; b < 6; b++)
            #pragma unroll
            for (int c = 0; c < 4; c++) acc[a][b][c] = 0.f;

    const int n0 = blockIdx.x * 96;
    const int m0 = blockIdx.y * 128;
    run_gemm(g_ao, fc_w, m0, n0, &sm.g, acc);

    const int lane = threadIdx.x & 31, wid = threadIdx.x >> 5;
    const int wm = wid & 3, wn = wid >> 2;
    const int rr = lane >> 2, c2 = (lane & 3) << 1;
    #pragma unroll
    for (int mt = 0; mt < 2; mt++)
        #pragma unroll
        for (int nt = 0; nt < 6; nt++) {
            int row = m0 + wm * 32 + mt * 16 + rr;
            int col = n0 + wn * 48 + nt * 8 + c2;
            float b0 = fc_b[col], b1 = fc_b[col + 1];
            float2 v0 = make_float2(acc[mt][nt][0] + b0, acc[mt][nt][1] + b1);
            float2 v1 = make_float2(acc[mt][nt][2] + b0, acc[mt][nt][3] + b1);
            *reinterpret_cast<float2*>(&out[(size_t)row * 384 + col])       = v0;
            *reinterpret_cast<float2*>(&out[(size_t)(row + 8) * 384 + col]) = v1;
        }
}

// ---------------- launch ----------------
extern "C" void kernel_launch(void* const* d_in, const int* in_sizes, int n_in,
                              void* d_out, int out_size) {
    const float* x    = (const float*)d_in[0];
    const float* tbl  = (const float*)d_in[1];
    const float* qw   = (const float*)d_in[2];
    const float* qb   = (const float*)d_in[3];
    const float* fw   = (const float*)d_in[4];
    const float* fb   = (const float*)d_in[5];
    const int*   ridx = (const int*)d_in[6];
    float* out = (float*)d_out;

    bias_kernel<<<(NHEAD * NTOK * NTOK + 255) / 256, 256>>>(tbl, ridx);
    qkv_kernel<<<dim3(NHEAD, MTOT / 128), 256>>>(x, qw, qb);
    attn_kernel<<<NWIN * NHEAD, 128>>>();
    fc_kernel<<<dim3(HID / 96, MTOT / 128), 256>>>(fw, fb, out);
}

// round 10
// speedup vs baseline: 2.5630x; 1.0247x over previous
#include <cuda_runtime.h>
#include <cuda_fp16.h>
#include <cstdint>

// ---------------- problem constants ----------------
#define NWIN    4096
#define NTOK    49
#define HID     384
#define NHEAD   12
#define DHEAD   32
#define MTOT    (NWIN*NTOK)          // 200704
#define QSCALE  0.17677669529663687f // 32^-0.5

// ---------------- device scratch ----------------
__device__ float g_q[(size_t)MTOT * HID];    // [win][head][tok][d]
__device__ float g_k[(size_t)MTOT * HID];
__device__ float g_v[(size_t)MTOT * HID];
__device__ float g_ao[(size_t)MTOT * HID];   // attention output [m][h*32+d]
__device__ float g_bias[NHEAD * NTOK * NTOK];

// ---------------- shared memory layout for GEMM kernels ----------------
struct SmemGemm {
    __half Ah[128 * 40];
    __half Al[128 * 40];
    __half Bh[96 * 40];
    __half Bl[96 * 40];
};
union SmemU {
    SmemGemm g;
    float    c[128 * 96];
};

// ---------------- mma.sync m16n8k16 fp16 -> fp32 ----------------
__device__ __forceinline__ void mma_f16(float c[4], const uint32_t a[4], const uint32_t b[2]) {
    asm volatile(
        "mma.sync.aligned.m16n8k16.row.col.f32.f16.f16.f32 "
        "{%0,%1,%2,%3}, {%4,%5,%6,%7}, {%8,%9}, {%0,%1,%2,%3};\n"
        : "+f"(c[0]), "+f"(c[1]), "+f"(c[2]), "+f"(c[3])
        : "r"(a[0]), "r"(a[1]), "r"(a[2]), "r"(a[3]),
          "r"(b[0]), "r"(b[1]));
}

__device__ __forceinline__ void ldsm4(uint32_t r[4], uint32_t addr) {
    asm volatile("ldmatrix.sync.aligned.m8n8.x4.shared.b16 {%0,%1,%2,%3}, [%4];\n"
                 : "=r"(r[0]), "=r"(r[1]), "=r"(r[2]), "=r"(r[3]) : "r"(addr));
}

__device__ __forceinline__ uint32_t ld_h2(const __half* p) {
    return *reinterpret_cast<const uint32_t*>(p);
}

__device__ __forceinline__ void split_store(__half* hi, __half* lo, float a, float b) {
    __half2 h, l;
    h.x = __float2half_rn(a); l.x = __float2half_rn(a - __half2float(h.x));
    h.y = __float2half_rn(b); l.y = __float2half_rn(b - __half2float(h.y));
    *reinterpret_cast<__half2*>(hi) = h;
    *reinterpret_cast<__half2*>(lo) = l;
}

__device__ __forceinline__ void cp16(uint32_t smem_addr, const void* gptr) {
    asm volatile("cp.async.cg.shared.global [%0], [%1], 16;\n"
                 :: "r"(smem_addr), "l"(gptr));
}

// ---------------- shared GEMM mainloop (K1/K3): C[128x96] = A * B^T ----------------
// Fragment loads via ldmatrix.x4: A 16x16 tile per op, B 16n x 16k per op.
// Stride 40 halves (80 B) -> LDSM row banks {0,20,8,28,16,4,24,12}: conflict-free.
__device__ __forceinline__ void run_gemm(const float* __restrict__ A,
                                         const float* __restrict__ B,
                                         int m0, int n0,
                                         SmemGemm* sm, float acc[2][6][4]) {
    const int tid  = threadIdx.x;
    const int lane = tid & 31;
    const int wid  = tid >> 5;
    const int wm   = wid & 3;
    const int wn   = wid >> 2;
    const int lr   = tid >> 3;
    const int lc   = (tid & 7) << 2;

    const float* Abase = A + (size_t)(m0 + lr) * 384 + lc;
    const float* Bbase = B + (size_t)(n0 + lr) * 384 + lc;

    const uint32_t AhB = (uint32_t)__cvta_generic_to_shared(sm->Ah);
    const uint32_t AlB = (uint32_t)__cvta_generic_to_shared(sm->Al);
    const uint32_t BhB = (uint32_t)__cvta_generic_to_shared(sm->Bh);
    const uint32_t BlB = (uint32_t)__cvta_generic_to_shared(sm->Bl);

    // per-lane ldmatrix address components
    const int aRow = wm * 32 + (lane & 15);          // + mt*16
    const int aCol = (lane >> 4) << 3;               // 0 or 8
    const int bRow = wn * 48 + (lane & 7) + ((lane & 16) >> 1);  // + ntp*16
    const int bCol = lane & 8;                        // 0 or 8

    float4 ra[4], rb[3];
    #pragma unroll
    for (int p = 0; p < 4; p++)
        ra[p] = *reinterpret_cast<const float4*>(Abase + (size_t)p * 32 * 384);
    #pragma unroll
    for (int p = 0; p < 3; p++)
        rb[p] = *reinterpret_cast<const float4*>(Bbase + (size_t)p * 32 * 384);

    for (int k0 = 0; k0 < 384; k0 += 32) {
        __syncthreads();
        #pragma unroll
        for (int p = 0; p < 4; p++) {
            int row = lr + p * 32;
            split_store(&sm->Ah[row * 40 + lc],     &sm->Al[row * 40 + lc],     ra[p].x, ra[p].y);
            split_store(&sm->Ah[row * 40 + lc + 2], &sm->Al[row * 40 + lc + 2], ra[p].z, ra[p].w);
        }
        #pragma unroll
        for (int p = 0; p < 3; p++) {
            int row = lr + p * 32;
            split_store(&sm->Bh[row * 40 + lc],     &sm->Bl[row * 40 + lc],     rb[p].x, rb[p].y);
            split_store(&sm->Bh[row * 40 + lc + 2], &sm->Bl[row * 40 + lc + 2], rb[p].z, rb[p].w);
        }
        __syncthreads();

        if (k0 + 32 < 384) {
            #pragma unroll
            for (int p = 0; p < 4; p++)
                ra[p] = *reinterpret_cast<const float4*>(Abase + (size_t)p * 32 * 384 + k0 + 32);
            #pragma unroll
            for (int p = 0; p < 3; p++)
                rb[p] = *reinterpret_cast<const float4*>(Bbase + (size_t)p * 32 * 384 + k0 + 32);
        }

        #pragma unroll
        for (int ks = 0; ks < 32; ks += 16) {
            uint32_t ah[2][4], al[2][4], bh4[3][4], bl4[3][4];
            #pragma unroll
            for (int mt = 0; mt < 2; mt++) {
                const uint32_t aoff = (uint32_t)(((aRow + mt * 16) * 40 + ks + aCol) * 2);
                ldsm4(ah[mt], AhB + aoff);
                ldsm4(al[mt], AlB + aoff);
            }
            #pragma unroll
            for (int ntp = 0; ntp < 3; ntp++) {
                const uint32_t boff = (uint32_t)(((bRow + ntp * 16) * 40 + ks + bCol) * 2);
                ldsm4(bh4[ntp], BhB + boff);
                ldsm4(bl4[ntp], BlB + boff);
            }
            #pragma unroll
            for (int mt = 0; mt < 2; mt++)
                #pragma unroll
                for (int nt = 0; nt < 6; nt++) {
                    const uint32_t* bh = &bh4[nt >> 1][(nt & 1) * 2];
                    const uint32_t* bl = &bl4[nt >> 1][(nt & 1) * 2];
                    mma_f16(acc[mt][nt], ah[mt], bh);
                    mma_f16(acc[mt][nt], ah[mt], bl);
                    mma_f16(acc[mt][nt], al[mt], bh);
                }
        }
    }
}

// ---------------- K0: dense relative position bias ----------------
__global__ void bias_kernel(const float* __restrict__ table, const int* __restrict__ ridx) {
    int e = blockIdx.x * 256 + threadIdx.x;
    if (e < NHEAD * NTOK * NTOK) {
        int h = e / (NTOK * NTOK);
        int r = e - h * (NTOK * NTOK);
        g_bias[e] = table[ridx[r] * NHEAD + h];
    }
}

// ---------------- K1: QKV projection + scatter ----------------
__global__ void __launch_bounds__(256) qkv_kernel(const float* __restrict__ x,
                                                  const float* __restrict__ qkv_w,
                                                  const float* __restrict__ qkv_b) {
    __shared__ SmemU sm;
    float acc[2][6][4];
    #pragma unroll
    for (int a = 0; a < 2; a++)
        #pragma unroll
        for (int b = 0; b < 6; b++)
            #pragma unroll
            for (int c = 0; c < 4; c++) acc[a][b][c] = 0.f;

    const int n0 = blockIdx.x * 96;
    const int m0 = blockIdx.y * 128;
    run_gemm(x, qkv_w, m0, n0, &sm.g, acc);
    __syncthreads();

    const int lane = threadIdx.x & 31, wid = threadIdx.x >> 5;
    const int wm = wid & 3, wn = wid >> 2;
    const int rr = lane >> 2, c2 = (lane & 3) << 1;
    #pragma unroll
    for (int mt = 0; mt < 2; mt++)
        #pragma unroll
        for (int nt = 0; nt < 6; nt++) {
            int row = wm * 32 + mt * 16 + rr;
            int col = wn * 48 + nt * 8 + c2;
            sm.c[row * 96 + col]           = acc[mt][nt][0];
            sm.c[row * 96 + col + 1]       = acc[mt][nt][1];
            sm.c[(row + 8) * 96 + col]     = acc[mt][nt][2];
            sm.c[(row + 8) * 96 + col + 1] = acc[mt][nt][3];
        }
    __syncthreads();

    const int h = blockIdx.x;
    for (int e = threadIdx.x; e < 128 * 96; e += 256) {
        int dd  = e & 31;
        int t2  = e >> 5;
        int s   = t2 % 3;
        int row = t2 / 3;
        int col = dd * 3 + s;
        float val = sm.c[row * 96 + col] + qkv_b[n0 + col];
        int m = m0 + row;
        int ww = m / 49;
        int t  = m - ww * 49;
        size_t o = ((size_t)(ww * NHEAD + h) * NTOK + t) * DHEAD + dd;
        if (s == 0)      __stcs(&g_q[o], val * QSCALE);
        else if (s == 1) __stcs(&g_k[o], val);
        else             __stcs(&g_v[o], val);
    }
}

// ---------------- K2: per-(window,head) attention via fp16-split MMA ----------------
// cp.async staged loads: q,k staged into sc region; v staged into Kh/Kl region.
struct AttnSmem {
    union {
        struct {
            __half Qh[64 * 40];   //     0 ..  5120
            __half Ql[64 * 40];   //  5120 .. 10240
            __half Kh[64 * 40];   // 10240 .. 15360
            __half Kl[64 * 40];   // 15360 .. 20480
        } qk;
        struct {
            __half Ph[64 * 72];
            __half Pl[64 * 72];
        } p;
    } u;                   // 20480 B
    __half Vth[32 * 72];   // 20480 .. 25088  (V transposed [d][token], hi)
    __half Vtl[32 * 72];   // 25088 .. 29696  (lo)
    float  sc[64 * 57];    // 29696 .. 44288  (staging q/k, then raw scores)
};

__global__ void __launch_bounds__(128) attn_kernel() {
    const int bid = blockIdx.x;        // ww*NHEAD + h
    const int h   = bid % NHEAD;
    const int ww  = bid / NHEAD;

    __shared__ AttnSmem s;

    const int tid = threadIdx.x, lane = tid & 31, wm = tid >> 5;
    const int rr  = lane >> 2;
    const int qoff = (lane & 3) << 1;
    const size_t base = (size_t)bid * (NTOK * DHEAD);

    // staging addresses (shared-space u32)
    const uint32_t stage_q = (uint32_t)__cvta_generic_to_shared(s.sc);                 // 6272 B
    const uint32_t stage_k = stage_q + 6272;                                           // 6272 B
    const uint32_t stage_v = (uint32_t)__cvta_generic_to_shared(s.u.qk.Kh);            // 6272 B

    // issue async copies of q/k/v (392 x 16B each), then zero Vth/Vtl pads
    {
        const char* gq = (const char*)(g_q + base);
        const char* gk = (const char*)(g_k + base);
        const char* gv = (const char*)(g_v + base);
        for (int e = tid; e < 392; e += 128) {
            cp16(stage_q + e * 16, gq + e * 16);
            cp16(stage_k + e * 16, gk + e * 16);
            cp16(stage_v + e * 16, gv + e * 16);
        }
        asm volatile("cp.async.commit_group;\n");
        // zero Vt (incl. pad token-cols 49..63): 9216 B, disjoint from staging
        uint4* z = reinterpret_cast<uint4*>(s.Vth);
        for (int i = tid; i < 9216 / 16; i += 128) z[i] = make_uint4(0, 0, 0, 0);
        asm volatile("cp.async.wait_group 0;\n" ::: "memory");
    }
    __syncthreads();

    // phase 1: convert V (from staging in Kh/Kl region) -> Vth/Vtl
    {
        const float* sv = (const float*)s.u.qk.Kh;
        for (int e = tid; e < 392; e += 128) {
            int j = e >> 3;               // token 0..48
            int c = (e & 7) << 2;         // d 0,4..28
            float4 v4 = *reinterpret_cast<const float4*>(sv + e * 4);
            const float* vv = &v4.x;
            #pragma unroll
            for (int l = 0; l < 4; l++) {
                float val = vv[l];
                __half hi = __float2half_rn(val);
                __half lo = __float2half_rn(val - __half2float(hi));
                s.Vth[(c + l) * 72 + j] = hi;
                s.Vtl[(c + l) * 72 + j] = lo;
            }
        }
    }
    __syncthreads();

    // phase 2: convert Q and K (sources in sc staging, targets in u.qk)
    {
        const float* sq = (const float*)s.sc;
        const float* sk = sq + 1568;
        for (int e = tid; e < 392; e += 128) {
            int j = e >> 3;
            int c = (e & 7) << 2;
            float4 q4 = *reinterpret_cast<const float4*>(sq + e * 4);
            float4 k4 = *reinterpret_cast<const float4*>(sk + e * 4);
            split_store(&s.u.qk.Qh[j * 40 + c],     &s.u.qk.Ql[j * 40 + c],     q4.x, q4.y);
            split_store(&s.u.qk.Qh[j * 40 + c + 2], &s.u.qk.Ql[j * 40 + c + 2], q4.z, q4.w);
            split_store(&s.u.qk.Kh[j * 40 + c],     &s.u.qk.Kl[j * 40 + c],     k4.x, k4.y);
            split_store(&s.u.qk.Kh[j * 40 + c + 2], &s.u.qk.Kl[j * 40 + c + 2], k4.z, k4.w);
        }
    }
    __syncthreads();

    // ---- scores: S[64x56] = Q @ K^T (warp wm owns rows wm*16..+15) ----
    {
        float acc[7][4];
        #pragma unroll
        for (int nt = 0; nt < 7; nt++)
            #pragma unroll
            for (int c = 0; c < 4; c++) acc[nt][c] = 0.f;

        #pragma unroll
        for (int kt = 0; kt < 32; kt += 16) {
            uint32_t ah[4], al[4];
            const int rb = wm * 16 + rr;
            const int cc = kt + qoff;
            ah[0] = ld_h2(&s.u.qk.Qh[rb * 40 + cc]);
            ah[1] = ld_h2(&s.u.qk.Qh[(rb + 8) * 40 + cc]);
            ah[2] = ld_h2(&s.u.qk.Qh[rb * 40 + cc + 8]);
            ah[3] = ld_h2(&s.u.qk.Qh[(rb + 8) * 40 + cc + 8]);
            al[0] = ld_h2(&s.u.qk.Ql[rb * 40 + cc]);
            al[1] = ld_h2(&s.u.qk.Ql[(rb + 8) * 40 + cc]);
            al[2] = ld_h2(&s.u.qk.Ql[rb * 40 + cc + 8]);
            al[3] = ld_h2(&s.u.qk.Ql[(rb + 8) * 40 + cc + 8]);
            #pragma unroll
            for (int nt = 0; nt < 7; nt++) {
                const int nb = nt * 8 + rr;
                uint32_t bh[2], bl[2];
                bh[0] = ld_h2(&s.u.qk.Kh[nb * 40 + cc]);
                bh[1] = ld_h2(&s.u.qk.Kh[nb * 40 + cc + 8]);
                bl[0] = ld_h2(&s.u.qk.Kl[nb * 40 + cc]);
                bl[1] = ld_h2(&s.u.qk.Kl[nb * 40 + cc + 8]);
                mma_f16(acc[nt], ah, bh);
                mma_f16(acc[nt], ah, bl);
                mma_f16(acc[nt], al, bh);
            }
        }
        __syncthreads();   // staging in sc fully consumed before overwriting with scores
        const int r0 = wm * 16 + rr;
        #pragma unroll
        for (int nt = 0; nt < 7; nt++) {
            const int c = nt * 8 + qoff;
            s.sc[r0 * 57 + c]           = acc[nt][0];
            s.sc[r0 * 57 + c + 1]       = acc[nt][1];
            s.sc[(r0 + 8) * 57 + c]     = acc[nt][2];
            s.sc[(r0 + 8) * 57 + c + 1] = acc[nt][3];
        }
    }
    __syncthreads();

    // ---- softmax (+bias) rows, write P split fp16 into union (Q/K dead) ----
    const float* bias = &g_bias[h * (NTOK * NTOK)];
    for (int i = wm; i < NTOK; i += 4) {
        const int j2 = 32 + lane;
        const bool v2 = (j2 < NTOK);
        float s0 = s.sc[i * 57 + lane] + bias[i * 49 + lane];
        float s1 = v2 ? (s.sc[i * 57 + j2] + bias[i * 49 + j2]) : -3.0e38f;
        float mx = fmaxf(s0, s1);
        #pragma unroll
        for (int o = 16; o; o >>= 1) mx = fmaxf(mx, __shfl_xor_sync(0xffffffffu, mx, o));
        float p0 = expf(s0 - mx);
        float p1 = v2 ? expf(s1 - mx) : 0.f;
        float sum = p0 + p1;
        #pragma unroll
        for (int o = 16; o; o >>= 1) sum += __shfl_xor_sync(0xffffffffu, sum, o);
        float inv = 1.f / sum;
        p0 *= inv;
        p1 = v2 ? p1 * inv : 0.f;
        {
            __half hi = __float2half_rn(p0);
            __half lo = __float2half_rn(p0 - __half2float(hi));
            s.u.p.Ph[i * 72 + lane] = hi;
            s.u.p.Pl[i * 72 + lane] = lo;
            __half hi1 = __float2half_rn(p1);
            __half lo1 = __float2half_rn(p1 - __half2float(hi1));
            s.u.p.Ph[i * 72 + j2] = hi1;
            s.u.p.Pl[i * 72 + j2] = lo1;
        }
    }
    __syncthreads();

    // ---- PV: O[64x32] = P[64x64] @ V  (Vt is col-major B) ----
    {
        float acc[4][4];
        #pragma unroll
        for (int nt = 0; nt < 4; nt++)
            #pragma unroll
            for (int c = 0; c < 4; c++) acc[nt][c] = 0.f;

        #pragma unroll
        for (int kt = 0; kt < 64; kt += 16) {
            uint32_t ah[4], al[4];
            const int rb = wm * 16 + rr;
            const int cc = kt + qoff;
            ah[0] = ld_h2(&s.u.p.Ph[rb * 72 + cc]);
            ah[1] = ld_h2(&s.u.p.Ph[(rb + 8) * 72 + cc]);
            ah[2] = ld_h2(&s.u.p.Ph[rb * 72 + cc + 8]);
            ah[3] = ld_h2(&s.u.p.Ph[(rb + 8) * 72 + cc + 8]);
            al[0] = ld_h2(&s.u.p.Pl[rb * 72 + cc]);
            al[1] = ld_h2(&s.u.p.Pl[(rb + 8) * 72 + cc]);
            al[2] = ld_h2(&s.u.p.Pl[rb * 72 + cc + 8]);
            al[3] = ld_h2(&s.u.p.Pl[(rb + 8) * 72 + cc + 8]);
            #pragma unroll
            for (int nt = 0; nt < 4; nt++) {
                const int nb = nt * 8 + rr;
                uint32_t bh[2], bl[2];
                bh[0] = ld_h2(&s.Vth[nb * 72 + cc]);
                bh[1] = ld_h2(&s.Vth[nb * 72 + cc + 8]);
                bl[0] = ld_h2(&s.Vtl[nb * 72 + cc]);
                bl[1] = ld_h2(&s.Vtl[nb * 72 + cc + 8]);
                mma_f16(acc[nt], ah, bh);
                mma_f16(acc[nt], ah, bl);
                mma_f16(acc[nt], al, bh);
            }
        }
        const int r0 = wm * 16 + rr;
        #pragma unroll
        for (int nt = 0; nt < 4; nt++) {
            const int d = nt * 8 + qoff;
            if (r0 < NTOK) {
                float2 v = make_float2(acc[nt][0], acc[nt][1]);
                *reinterpret_cast<float2*>(&g_ao[((size_t)ww * NTOK + r0) * HID + h * DHEAD + d]) = v;
            }
            if (r0 + 8 < NTOK) {
                float2 v = make_float2(acc[nt][2], acc[nt][3]);
                *reinterpret_cast<float2*>(&g_ao[((size_t)ww * NTOK + r0 + 8) * HID + h * DHEAD + d]) = v;
            }
        }
    }
}

// ---------------- K3: output projection ----------------
__global__ void __launch_bounds__(256) fc_kernel(const float* __restrict__ fc_w,
                                                 const float* __restrict__ fc_b,
                                                 float* __restrict__ out) {
    __shared__ SmemU sm;
    float acc[2][6][4];
    #pragma unroll
    for (int a = 0; a < 2; a++)
        #pragma unroll
        for (int b = 0; b < 6; b++)
            #pragma unroll
            for (int c = 0; c < 4; c++) acc[a][b][c] = 0.f;

    const int n0 = blockIdx.x * 96;
    const int m0 = blockIdx.y * 128;
    run_gemm(g_ao, fc_w, m0, n0, &sm.g, acc);

    const int lane = threadIdx.x & 31, wid = threadIdx.x >> 5;
    const int wm = wid & 3, wn = wid >> 2;
    const int rr = lane >> 2, c2 = (lane & 3) << 1;
    #pragma unroll
    for (int mt = 0; mt < 2; mt++)
        #pragma unroll
        for (int nt = 0; nt < 6; nt++) {
            int row = m0 + wm * 32 + mt * 16 + rr;
            int col = n0 + wn * 48 + nt * 8 + c2;
            float b0 = fc_b[col], b1 = fc_b[col + 1];
            float2 v0 = make_float2(acc[mt][nt][0] + b0, acc[mt][nt][1] + b1);
            float2 v1 = make_float2(acc[mt][nt][2] + b0, acc[mt][nt][3] + b1);
            *reinterpret_cast<float2*>(&out[(size_t)row * 384 + col])       = v0;
            *reinterpret_cast<float2*>(&out[(size_t)(row + 8) * 384 + col]) = v1;
        }
}

// ---------------- launch ----------------
extern "C" void kernel_launch(void* const* d_in, const int* in_sizes, int n_in,
                              void* d_out, int out_size) {
    const float* x    = (const float*)d_in[0];
    const float* tbl  = (const float*)d_in[1];
    const float* qw   = (const float*)d_in[2];
    const float* qb   = (const float*)d_in[3];
    const float* fw   = (const float*)d_in[4];
    const float* fb   = (const float*)d_in[5];
    const int*   ridx = (const int*)d_in[6];
    float* out = (float*)d_out;

    bias_kernel<<<(NHEAD * NTOK * NTOK + 255) / 256, 256>>>(tbl, ridx);
    qkv_kernel<<<dim3(NHEAD, MTOT / 128), 256>>>(x, qw, qb);
    attn_kernel<<<NWIN * NHEAD, 128>>>();
    fc_kernel<<<dim3(HID / 96, MTOT / 128), 256>>>(fw, fb, out);
}

// round 12
// speedup vs baseline: 2.5763x; 1.0052x over previous
#include <cuda_runtime.h>
#include <cuda_fp16.h>
#include <cstdint>

// ---------------- problem constants ----------------
#define NWIN    4096
#define NTOK    49
#define HID     384
#define NHEAD   12
#define DHEAD   32
#define MTOT    (NWIN*NTOK)          // 200704
#define QSCALE  0.17677669529663687f // 32^-0.5

#define NBH     (NWIN*NHEAD)         // 49152
#define QK_STRIDE (49*40)            // halves per (w,h) planar q/k array
#define VT_STRIDE (32*72)            // halves per (w,h) transposed v array

// ---------------- device scratch ----------------
// q/k stored pre-split planar hi/lo in attn's smem layout [t*40+d].
// v stored pre-split, pre-transposed [d*72+t]; pad cols 49..71 are NEVER
// written -> remain zero from .bss init (NaN guard for PV pads).
__device__ __half g_qh[(size_t)NBH * QK_STRIDE];
__device__ __half g_ql[(size_t)NBH * QK_STRIDE];
__device__ __half g_kh[(size_t)NBH * QK_STRIDE];
__device__ __half g_kl[(size_t)NBH * QK_STRIDE];
__device__ __half g_vth[(size_t)NBH * VT_STRIDE];
__device__ __half g_vtl[(size_t)NBH * VT_STRIDE];
__device__ float g_ao[(size_t)MTOT * HID];   // attention output [m][h*32+d]
__device__ float g_bias[NHEAD * NTOK * NTOK];

// ---------------- shared memory layout for GEMM kernels ----------------
struct SmemGemm {
    __half Ah[128 * 40];
    __half Al[128 * 40];
    __half Bh[96 * 40];
    __half Bl[96 * 40];
};
union SmemU {
    SmemGemm g;
    float    c[128 * 96];
};

// ---------------- mma.sync m16n8k16 fp16 -> fp32 ----------------
__device__ __forceinline__ void mma_f16(float c[4], const uint32_t a[4], const uint32_t b[2]) {
    asm volatile(
        "mma.sync.aligned.m16n8k16.row.col.f32.f16.f16.f32 "
        "{%0,%1,%2,%3}, {%4,%5,%6,%7}, {%8,%9}, {%0,%1,%2,%3};\n"
        : "+f"(c[0]), "+f"(c[1]), "+f"(c[2]), "+f"(c[3])
        : "r"(a[0]), "r"(a[1]), "r"(a[2]), "r"(a[3]),
          "r"(b[0]), "r"(b[1]));
}

__device__ __forceinline__ void ldsm4(uint32_t r[4], uint32_t addr) {
    asm volatile("ldmatrix.sync.aligned.m8n8.x4.shared.b16 {%0,%1,%2,%3}, [%4];\n"
                 : "=r"(r[0]), "=r"(r[1]), "=r"(r[2]), "=r"(r[3]) : "r"(addr));
}

__device__ __forceinline__ uint32_t ld_h2(const __half* p) {
    return *reinterpret_cast<const uint32_t*>(p);
}

__device__ __forceinline__ void split_store(__half* hi, __half* lo, float a, float b) {
    __half2 h, l;
    h.x = __float2half_rn(a); l.x = __float2half_rn(a - __half2float(h.x));
    h.y = __float2half_rn(b); l.y = __float2half_rn(b - __half2float(h.y));
    *reinterpret_cast<__half2*>(hi) = h;
    *reinterpret_cast<__half2*>(lo) = l;
}

__device__ __forceinline__ void cp16(uint32_t smem_addr, const void* gptr) {
    asm volatile("cp.async.cg.shared.global [%0], [%1], 16;\n"
                 :: "r"(smem_addr), "l"(gptr));
}

// ---------------- shared GEMM mainloop (K1/K3): C[128x96] = A * B^T ----------------
__device__ __forceinline__ void run_gemm(const float* __restrict__ A,
                                         const float* __restrict__ B,
                                         int m0, int n0,
                                         SmemGemm* sm, float acc[2][6][4]) {
    const int tid  = threadIdx.x;
    const int lane = tid & 31;
    const int wid  = tid >> 5;
    const int wm   = wid & 3;
    const int wn   = wid >> 2;
    const int lr   = tid >> 3;
    const int lc   = (tid & 7) << 2;

    const float* Abase = A + (size_t)(m0 + lr) * 384 + lc;
    const float* Bbase = B + (size_t)(n0 + lr) * 384 + lc;

    const uint32_t AhB = (uint32_t)__cvta_generic_to_shared(sm->Ah);
    const uint32_t AlB = (uint32_t)__cvta_generic_to_shared(sm->Al);
    const uint32_t BhB = (uint32_t)__cvta_generic_to_shared(sm->Bh);
    const uint32_t BlB = (uint32_t)__cvta_generic_to_shared(sm->Bl);

    const int aRow = wm * 32 + (lane & 15);
    const int aCol = (lane >> 4) << 3;
    const int bRow = wn * 48 + (lane & 7) + ((lane & 16) >> 1);
    const int bCol = lane & 8;

    float4 ra[4], rb[3];
    #pragma unroll
    for (int p = 0; p < 4; p++)
        ra[p] = *reinterpret_cast<const float4*>(Abase + (size_t)p * 32 * 384);
    #pragma unroll
    for (int p = 0; p < 3; p++)
        rb[p] = *reinterpret_cast<const float4*>(Bbase + (size_t)p * 32 * 384);

    for (int k0 = 0; k0 < 384; k0 += 32) {
        __syncthreads();
        #pragma unroll
        for (int p = 0; p < 4; p++) {
            int row = lr + p * 32;
            split_store(&sm->Ah[row * 40 + lc],     &sm->Al[row * 40 + lc],     ra[p].x, ra[p].y);
            split_store(&sm->Ah[row * 40 + lc + 2], &sm->Al[row * 40 + lc + 2], ra[p].z, ra[p].w);
        }
        #pragma unroll
        for (int p = 0; p < 3; p++) {
            int row = lr + p * 32;
            split_store(&sm->Bh[row * 40 + lc],     &sm->Bl[row * 40 + lc],     rb[p].x, rb[p].y);
            split_store(&sm->Bh[row * 40 + lc + 2], &sm->Bl[row * 40 + lc + 2], rb[p].z, rb[p].w);
        }
        __syncthreads();

        if (k0 + 32 < 384) {
            #pragma unroll
            for (int p = 0; p < 4; p++)
                ra[p] = *reinterpret_cast<const float4*>(Abase + (size_t)p * 32 * 384 + k0 + 32);
            #pragma unroll
            for (int p = 0; p < 3; p++)
                rb[p] = *reinterpret_cast<const float4*>(Bbase + (size_t)p * 32 * 384 + k0 + 32);
        }

        #pragma unroll
        for (int ks = 0; ks < 32; ks += 16) {
            uint32_t ah[2][4], al[2][4], bh4[3][4], bl4[3][4];
            #pragma unroll
            for (int mt = 0; mt < 2; mt++) {
                const uint32_t aoff = (uint32_t)(((aRow + mt * 16) * 40 + ks + aCol) * 2);
                ldsm4(ah[mt], AhB + aoff);
                ldsm4(al[mt], AlB + aoff);
            }
            #pragma unroll
            for (int ntp = 0; ntp < 3; ntp++) {
                const uint32_t boff = (uint32_t)(((bRow + ntp * 16) * 40 + ks + bCol) * 2);
                ldsm4(bh4[ntp], BhB + boff);
                ldsm4(bl4[ntp], BlB + boff);
            }
            #pragma unroll
            for (int mt = 0; mt < 2; mt++)
                #pragma unroll
                for (int nt = 0; nt < 6; nt++) {
                    const uint32_t* bh = &bh4[nt >> 1][(nt & 1) * 2];
                    const uint32_t* bl = &bl4[nt >> 1][(nt & 1) * 2];
                    mma_f16(acc[mt][nt], ah[mt], bh);
                    mma_f16(acc[mt][nt], ah[mt], bl);
                    mma_f16(acc[mt][nt], al[mt], bh);
                }
        }
    }
}

// ---------------- K0: dense relative position bias ----------------
__global__ void bias_kernel(const float* __restrict__ table, const int* __restrict__ ridx) {
    int e = blockIdx.x * 256 + threadIdx.x;
    if (e < NHEAD * NTOK * NTOK) {
        int h = e / (NTOK * NTOK);
        int r = e - h * (NTOK * NTOK);
        g_bias[e] = table[ridx[r] * NHEAD + h];
    }
}

// ---------------- K1: QKV projection + split scatter ----------------
__global__ void __launch_bounds__(256) qkv_kernel(const float* __restrict__ x,
                                                  const float* __restrict__ qkv_w,
                                                  const float* __restrict__ qkv_b) {
    __shared__ SmemU sm;
    float acc[2][6][4];
    #pragma unroll
    for (int a = 0; a < 2; a++)
        #pragma unroll
        for (int b = 0; b < 6; b++)
            #pragma unroll
            for (int c = 0; c < 4; c++) acc[a][b][c] = 0.f;

    const int n0 = blockIdx.x * 96;
    const int m0 = blockIdx.y * 128;
    run_gemm(x, qkv_w, m0, n0, &sm.g, acc);
    __syncthreads();

    const int lane = threadIdx.x & 31, wid = threadIdx.x >> 5;
    const int wm = wid & 3, wn = wid >> 2;
    const int rr = lane >> 2, c2 = (lane & 3) << 1;
    #pragma unroll
    for (int mt = 0; mt < 2; mt++)
        #pragma unroll
        for (int nt = 0; nt < 6; nt++) {
            int row = wm * 32 + mt * 16 + rr;
            int col = wn * 48 + nt * 8 + c2;
            sm.c[row * 96 + col]           = acc[mt][nt][0];
            sm.c[row * 96 + col + 1]       = acc[mt][nt][1];
            sm.c[(row + 8) * 96 + col]     = acc[mt][nt][2];
            sm.c[(row + 8) * 96 + col + 1] = acc[mt][nt][3];
        }
    __syncthreads();

    const int h = blockIdx.x;
    // q,k: split hi/lo, planar layout [w,h][t*40+dd]; coalesced over dd
    for (int e = threadIdx.x; e < 128 * 64; e += 256) {
        int dd  = e & 31;
        int sp  = (e >> 5) & 1;
        int row = e >> 6;
        int col = dd * 3 + sp;
        float val = sm.c[row * 96 + col] + qkv_b[n0 + col];
        if (sp == 0) val *= QSCALE;
        __half hi = __float2half_rn(val);
        __half lo = __float2half_rn(val - __half2float(hi));
        int m = m0 + row;
        int ww = m / 49;
        int t  = m - ww * 49;
        size_t o = (size_t)(ww * NHEAD + h) * QK_STRIDE + t * 40 + dd;
        if (sp == 0) { g_qh[o] = hi; g_ql[o] = lo; }
        else         { g_kh[o] = hi; g_kl[o] = lo; }
    }
    // v: transposed layout [w,h][dd*72+t]; coalesced over t (row fastest)
    for (int e = threadIdx.x; e < 128 * 32; e += 256) {
        int row = e & 127;
        int dd  = e >> 7;
        int col = dd * 3 + 2;
        float val = sm.c[row * 96 + col] + qkv_b[n0 + col];
        __half hi = __float2half_rn(val);
        __half lo = __float2half_rn(val - __half2float(hi));
        int m = m0 + row;
        int ww = m / 49;
        int t  = m - ww * 49;
        size_t o = (size_t)(ww * NHEAD + h) * VT_STRIDE + dd * 72 + t;
        g_vth[o] = hi;
        g_vtl[o] = lo;
    }
}

// ---------------- K2: per-(window,head) attention via fp16-split MMA ----------------
struct AttnSmem {
    union {
        struct {
            __half Qh[64 * 40];
            __half Ql[64 * 40];
            __half Kh[64 * 40];
            __half Kl[64 * 40];
        } qk;
        struct {
            __half Ph[64 * 72];
            __half Pl[64 * 72];
        } p;
    } u;                   // 20480 B
    __half Vth[32 * 72];
    __half Vtl[32 * 72];
    float  sc[64 * 57];
};

__global__ void __launch_bounds__(128) attn_kernel() {
    const int bid = blockIdx.x;        // ww*NHEAD + h
    const int h   = bid % NHEAD;
    const int ww  = bid / NHEAD;

    __shared__ AttnSmem s;

    const int tid = threadIdx.x, lane = tid & 31, wm = tid >> 5;
    const int rr  = lane >> 2;
    const int qoff = (lane & 3) << 1;

    // direct cp.async of pre-split, pre-laid-out q/k/v
    {
        const uint32_t smQ = (uint32_t)__cvta_generic_to_shared(s.u.qk.Qh);
        const uint32_t smV = (uint32_t)__cvta_generic_to_shared(s.Vth);
        const char* gqh = (const char*)g_qh + (size_t)bid * (QK_STRIDE * 2);
        const char* gql = (const char*)g_ql + (size_t)bid * (QK_STRIDE * 2);
        const char* gkh = (const char*)g_kh + (size_t)bid * (QK_STRIDE * 2);
        const char* gkl = (const char*)g_kl + (size_t)bid * (QK_STRIDE * 2);
        const char* gvh = (const char*)g_vth + (size_t)bid * (VT_STRIDE * 2);
        const char* gvl = (const char*)g_vtl + (size_t)bid * (VT_STRIDE * 2);
        for (int e = tid; e < 245; e += 128) {         // 3920 B per q/k array
            cp16(smQ + e * 16,         gqh + e * 16);
            cp16(smQ + 5120 + e * 16,  gql + e * 16);
            cp16(smQ + 10240 + e * 16, gkh + e * 16);
            cp16(smQ + 15360 + e * 16, gkl + e * 16);
        }
        for (int e = tid; e < 288; e += 128) {         // 4608 B per vt array (pads zero)
            cp16(smV + e * 16,        gvh + e * 16);
            cp16(smV + 4608 + e * 16, gvl + e * 16);
        }
        asm volatile("cp.async.commit_group;\n");
        asm volatile("cp.async.wait_group 0;\n" ::: "memory");
    }
    __syncthreads();

    // ---- scores: S[64x56] = Q @ K^T (warp wm owns rows wm*16..+15) ----
    {
        float acc[7][4];
        #pragma unroll
        for (int nt = 0; nt < 7; nt++)
            #pragma unroll
            for (int c = 0; c < 4; c++) acc[nt][c] = 0.f;

        #pragma unroll
        for (int kt = 0; kt < 32; kt += 16) {
            uint32_t ah[4], al[4];
            const int rb = wm * 16 + rr;
            const int cc = kt + qoff;
            ah[0] = ld_h2(&s.u.qk.Qh[rb * 40 + cc]);
            ah[1] = ld_h2(&s.u.qk.Qh[(rb + 8) * 40 + cc]);
            ah[2] = ld_h2(&s.u.qk.Qh[rb * 40 + cc + 8]);
            ah[3] = ld_h2(&s.u.qk.Qh[(rb + 8) * 40 + cc + 8]);
            al[0] = ld_h2(&s.u.qk.Ql[rb * 40 + cc]);
            al[1] = ld_h2(&s.u.qk.Ql[(rb + 8) * 40 + cc]);
            al[2] = ld_h2(&s.u.qk.Ql[rb * 40 + cc + 8]);
            al[3] = ld_h2(&s.u.qk.Ql[(rb + 8) * 40 + cc + 8]);
            #pragma unroll
            for (int nt = 0; nt < 7; nt++) {
                const int nb = nt * 8 + rr;
                uint32_t bh[2], bl[2];
                bh[0] = ld_h2(&s.u.qk.Kh[nb * 40 + cc]);
                bh[1] = ld_h2(&s.u.qk.Kh[nb * 40 + cc + 8]);
                bl[0] = ld_h2(&s.u.qk.Kl[nb * 40 + cc]);
                bl[1] = ld_h2(&s.u.qk.Kl[nb * 40 + cc + 8]);
                mma_f16(acc[nt], ah, bh);
                mma_f16(acc[nt], ah, bl);
                mma_f16(acc[nt], al, bh);
            }
        }
        const int r0 = wm * 16 + rr;
        #pragma unroll
        for (int nt = 0; nt < 7; nt++) {
            const int c = nt * 8 + qoff;
            s.sc[r0 * 57 + c]           = acc[nt][0];
            s.sc[r0 * 57 + c + 1]       = acc[nt][1];
            s.sc[(r0 + 8) * 57 + c]     = acc[nt][2];
            s.sc[(r0 + 8) * 57 + c + 1] = acc[nt][3];
        }
    }
    __syncthreads();

    // ---- softmax (+bias) rows, write P split fp16 into union (Q/K dead) ----
    const float* bias = &g_bias[h * (NTOK * NTOK)];
    for (int i = wm; i < NTOK; i += 4) {
        const int j2 = 32 + lane;
        const bool v2 = (j2 < NTOK);
        float s0 = s.sc[i * 57 + lane] + bias[i * 49 + lane];
        float s1 = v2 ? (s.sc[i * 57 + j2] + bias[i * 49 + j2]) : -3.0e38f;
        float mx = fmaxf(s0, s1);
        #pragma unroll
        for (int o = 16; o; o >>= 1) mx = fmaxf(mx, __shfl_xor_sync(0xffffffffu, mx, o));
        float p0 = expf(s0 - mx);
        float p1 = v2 ? expf(s1 - mx) : 0.f;
        float sum = p0 + p1;
        #pragma unroll
        for (int o = 16; o; o >>= 1) sum += __shfl_xor_sync(0xffffffffu, sum, o);
        float inv = 1.f / sum;
        p0 *= inv;
        p1 = v2 ? p1 * inv : 0.f;
        {
            __half hi = __float2half_rn(p0);
            __half lo = __float2half_rn(p0 - __half2float(hi));
            s.u.p.Ph[i * 72 + lane] = hi;
            s.u.p.Pl[i * 72 + lane] = lo;
            __half hi1 = __float2half_rn(p1);
            __half lo1 = __float2half_rn(p1 - __half2float(hi1));
            s.u.p.Ph[i * 72 + j2] = hi1;
            s.u.p.Pl[i * 72 + j2] = lo1;
        }
    }
    __syncthreads();

    // ---- PV: O[64x32] = P[64x64] @ V  (Vt is col-major B) ----
    {
        float acc[4][4];
        #pragma unroll
        for (int nt = 0; nt < 4; nt++)
            #pragma unroll
            for (int c = 0; c < 4; c++) acc[nt][c] = 0.f;

        #pragma unroll
        for (int kt = 0; kt < 64; kt += 16) {
            uint32_t ah[4], al[4];
            const int rb = wm * 16 + rr;
            const int cc = kt + qoff;
            ah[0] = ld_h2(&s.u.p.Ph[rb * 72 + cc]);
            ah[1] = ld_h2(&s.u.p.Ph[(rb + 8) * 72 + cc]);
            ah[2] = ld_h2(&s.u.p.Ph[rb * 72 + cc + 8]);
            ah[3] = ld_h2(&s.u.p.Ph[(rb + 8) * 72 + cc + 8]);
            al[0] = ld_h2(&s.u.p.Pl[rb * 72 + cc]);
            al[1] = ld_h2(&s.u.p.Pl[(rb + 8) * 72 + cc]);
            al[2] = ld_h2(&s.u.p.Pl[rb * 72 + cc + 8]);
            al[3] = ld_h2(&s.u.p.Pl[(rb + 8) * 72 + cc + 8]);
            #pragma unroll
            for (int nt = 0; nt < 4; nt++) {
                const int nb = nt * 8 + rr;
                uint32_t bh[2], bl[2];
                bh[0] = ld_h2(&s.Vth[nb * 72 + cc]);
                bh[1] = ld_h2(&s.Vth[nb * 72 + cc + 8]);
                bl[0] = ld_h2(&s.Vtl[nb * 72 + cc]);
                bl[1] = ld_h2(&s.Vtl[nb * 72 + cc + 8]);
                mma_f16(acc[nt], ah, bh);
                mma_f16(acc[nt], ah, bl);
                mma_f16(acc[nt], al, bh);
            }
        }
        const int r0 = wm * 16 + rr;
        #pragma unroll
        for (int nt = 0; nt < 4; nt++) {
            const int d = nt * 8 + qoff;
            if (r0 < NTOK) {
                float2 v = make_float2(acc[nt][0], acc[nt][1]);
                *reinterpret_cast<float2*>(&g_ao[((size_t)ww * NTOK + r0) * HID + h * DHEAD + d]) = v;
            }
            if (r0 + 8 < NTOK) {
                float2 v = make_float2(acc[nt][2], acc[nt][3]);
                *reinterpret_cast<float2*>(&g_ao[((size_t)ww * NTOK + r0 + 8) * HID + h * DHEAD + d]) = v;
            }
        }
    }
}

// ---------------- K3: output projection ----------------
__global__ void __launch_bounds__(256) fc_kernel(const float* __restrict__ fc_w,
                                                 const float* __restrict__ fc_b,
                                                 float* __restrict__ out) {
    __shared__ SmemU sm;
    float acc[2][6][4];
    #pragma unroll
    for (int a = 0; a < 2; a++)
        #pragma unroll
        for (int b = 0; b < 6; b++)
            #pragma unroll
            for (int c = 0; c < 4; c++) acc[a][b][c] = 0.f;

    const int n0 = blockIdx.x * 96;
    const int m0 = blockIdx.y * 128;
    run_gemm(g_ao, fc_w, m0, n0, &sm.g, acc);

    const int lane = threadIdx.x & 31, wid = threadIdx.x >> 5;
    const int wm = wid & 3, wn = wid >> 2;
    const int rr = lane >> 2, c2 = (lane & 3) << 1;
    #pragma unroll
    for (int mt = 0; mt < 2; mt++)
        #pragma unroll
        for (int nt = 0; nt < 6; nt++) {
            int row = m0 + wm * 32 + mt * 16 + rr;
            int col = n0 + wn * 48 + nt * 8 + c2;
            float b0 = fc_b[col], b1 = fc_b[col + 1];
            float2 v0 = make_float2(acc[mt][nt][0] + b0, acc[mt][nt][1] + b1);
            float2 v1 = make_float2(acc[mt][nt][2] + b0, acc[mt][nt][3] + b1);
            *reinterpret_cast<float2*>(&out[(size_t)row * 384 + col])       = v0;
            *reinterpret_cast<float2*>(&out[(size_t)(row + 8) * 384 + col]) = v1;
        }
}

// ---------------- launch ----------------
extern "C" void kernel_launch(void* const* d_in, const int* in_sizes, int n_in,
                              void* d_out, int out_size) {
    const float* x    = (const float*)d_in[0];
    const float* tbl  = (const float*)d_in[1];
    const float* qw   = (const float*)d_in[2];
    const float* qb   = (const float*)d_in[3];
    const float* fw   = (const float*)d_in[4];
    const float* fb   = (const float*)d_in[5];
    const int*   ridx = (const int*)d_in[6];
    float* out = (float*)d_out;

    bias_kernel<<<(NHEAD * NTOK * NTOK + 255) / 256, 256>>>(tbl, ridx);
    qkv_kernel<<<dim3(NHEAD, MTOT / 128), 256>>>(x, qw, qb);
    attn_kernel<<<NWIN * NHEAD, 128>>>();
    fc_kernel<<<dim3(HID / 96, MTOT / 128), 256>>>(fw, fb, out);
}